// round 3
// baseline (speedup 1.0000x reference)
#include <cuda_runtime.h>
#include <cstdint>

// Problem constants
#define Cc      128
#define Hh      256
#define Ww      256
#define Bb      4
#define PLANE   65536          // Hh*Ww
#define NPLANES 512            // Bb*Cc
#define TOTAL   33554432       // Bb*Cc*PLANE

// Scratch (allocation-free rule: __device__ globals)
__device__ float g_h[TOTAL];
__device__ float g_v[TOTAL];
__device__ float g_hpart[NPLANES * 64];
__device__ float g_vpart[NPLANES * 8];
__device__ float g_gate[Bb * 2];

// ---------------------------------------------------------------------------
// Kernel 1: horizontal chain  h = dw1x5(x) then dw1x7 dil3
// Block: (256,4) = 1024 threads, 4 rows of one (b,c) plane. Grid (64, 512).
// ---------------------------------------------------------------------------
__global__ __launch_bounds__(1024) void hconv_kernel(
    const float* __restrict__ x,
    const float* __restrict__ h1w,
    const float* __restrict__ h2w)
{
    const int plane = blockIdx.y;          // b*C + c
    const int rb    = blockIdx.x;          // row block (4 rows)
    const int c     = plane & (Cc - 1);
    const int tx    = threadIdx.x;
    const int ty    = threadIdx.y;
    const int row   = rb * 4 + ty;

    __shared__ float xs[4][Ww];
    __shared__ float ys[4][Ww];
    __shared__ float red[32];

    float w1[5], w2[7];
#pragma unroll
    for (int j = 0; j < 5; j++) w1[j] = h1w[c * 5 + j];
#pragma unroll
    for (int k = 0; k < 7; k++) w2[k] = h2w[c * 7 + k];

    const int base = plane * PLANE + row * Ww;
    xs[ty][tx] = x[base + tx];
    __syncthreads();

    float y = 0.f;
#pragma unroll
    for (int j = 0; j < 5; j++) {
        int cc = tx + j - 2;
        if (cc >= 0 && cc < Ww) y += xs[ty][cc] * w1[j];
    }
    ys[ty][tx] = y;
    __syncthreads();

    float hv = 0.f;
#pragma unroll
    for (int k = 0; k < 7; k++) {
        int cc = tx + 3 * k - 9;
        if (cc >= 0 && cc < Ww) hv += ys[ty][cc] * w2[k];
    }
    g_h[base + tx] = hv;

    // block reduction of hv over 1024 threads -> deterministic partial
    float s = hv;
#pragma unroll
    for (int o = 16; o > 0; o >>= 1) s += __shfl_down_sync(0xffffffffu, s, o);
    const int t    = ty * 256 + tx;
    const int wid  = t >> 5;
    const int lane = t & 31;
    if (lane == 0) red[wid] = s;
    __syncthreads();
    if (wid == 0) {
        float v = red[lane];
#pragma unroll
        for (int o = 16; o > 0; o >>= 1) v += __shfl_down_sync(0xffffffffu, v, o);
        if (lane == 0) g_hpart[plane * 64 + rb] = v;
    }
}

// ---------------------------------------------------------------------------
// Kernel 2: vertical chain  v = dw5x1(x) then dw7x1 dil3
// Block: 256 threads, tile = 32 cols x 256 rows of one plane. Grid (8, 512).
// Dynamic smem: xs[256*32] + ys[256*32] = 64 KB.
// ---------------------------------------------------------------------------
__global__ __launch_bounds__(256) void vconv_kernel(
    const float* __restrict__ x,
    const float* __restrict__ v1w,
    const float* __restrict__ v2w)
{
    extern __shared__ float vsm[];
    float* xs = vsm;           // [256][32]
    float* ys = vsm + 8192;    // [256][32]

    const int plane = blockIdx.y;
    const int tile  = blockIdx.x;
    const int c     = plane & (Cc - 1);
    const int c0    = tile * 32;
    const int t     = threadIdx.x;

    float w1[5], w2[7];
#pragma unroll
    for (int j = 0; j < 5; j++) w1[j] = v1w[c * 5 + j];
#pragma unroll
    for (int k = 0; k < 7; k++) w2[k] = v2w[c * 7 + k];

    const int pbase = plane * PLANE + c0;
    for (int i = t; i < 8192; i += 256) {
        int r = i >> 5, cl = i & 31;
        xs[i] = x[pbase + r * Ww + cl];
    }
    __syncthreads();

    const int rr = t >> 5;
    const int cl = t & 31;
    for (int r = rr; r < Hh; r += 8) {
        float s = 0.f;
#pragma unroll
        for (int j = 0; j < 5; j++) {
            int q = r + j - 2;
            if (q >= 0 && q < Hh) s += xs[q * 32 + cl] * w1[j];
        }
        ys[r * 32 + cl] = s;
    }
    __syncthreads();

    float acc = 0.f;
    for (int r = rr; r < Hh; r += 8) {
        float s = 0.f;
#pragma unroll
        for (int k = 0; k < 7; k++) {
            int q = r + 3 * k - 9;
            if (q >= 0 && q < Hh) s += ys[q * 32 + cl] * w2[k];
        }
        g_v[pbase + r * Ww + cl] = s;
        acc += s;
    }

    // block reduction (256 threads)
    __shared__ float red[8];
#pragma unroll
    for (int o = 16; o > 0; o >>= 1) acc += __shfl_down_sync(0xffffffffu, acc, o);
    const int wid = t >> 5, lane = t & 31;
    if (lane == 0) red[wid] = acc;
    __syncthreads();
    if (wid == 0) {
        float v = (lane < 8) ? red[lane] : 0.f;
#pragma unroll
        for (int o = 4; o > 0; o >>= 1) v += __shfl_down_sync(0xffffffffu, v, o);
        if (lane == 0) g_vpart[plane * 8 + tile] = v;
    }
}

// ---------------------------------------------------------------------------
// Kernel 3: gate. One block, 256 threads.
// pooled = [hmean, vmean] per batch -> g1 (32x256) -> SiLU -> g2 (2x32) -> softmax
// ---------------------------------------------------------------------------
__global__ __launch_bounds__(256) void gate_kernel(
    const float* __restrict__ g1w,
    const float* __restrict__ g2w,
    const float* __restrict__ g2b)
{
    __shared__ float pooled[Bb][2 * Cc];
    __shared__ float gs[Bb][32];
    const int t = threadIdx.x;
    const float inv = 1.0f / 65536.0f;

    for (int p = t; p < NPLANES; p += 256) {
        int b = p >> 7, c = p & 127;
        float hs = 0.f;
#pragma unroll
        for (int i = 0; i < 64; i++) hs += g_hpart[p * 64 + i];
        float vs = 0.f;
#pragma unroll
        for (int i = 0; i < 8; i++) vs += g_vpart[p * 8 + i];
        pooled[b][c]       = hs * inv;
        pooled[b][Cc + c]  = vs * inv;
    }
    __syncthreads();

    if (t < 128) {
        int b = t >> 5, j = t & 31;
        float s = 0.f;
        for (int i = 0; i < 2 * Cc; i++) s += pooled[b][i] * g1w[j * 256 + i];
        gs[b][j] = s / (1.0f + expf(-s));   // SiLU
    }
    __syncthreads();

    if (t < Bb) {
        int b = t;
        float l0 = g2b[0], l1 = g2b[1];
        for (int j = 0; j < 32; j++) {
            l0 += gs[b][j] * g2w[j];
            l1 += gs[b][j] * g2w[32 + j];
        }
        float m = fmaxf(l0, l1);
        float e0 = expf(l0 - m), e1 = expf(l1 - m);
        float d = e0 + e1;
        g_gate[b * 2 + 0] = e0 / d;
        g_gate[b * 2 + 1] = e1 / d;
    }
}

// ---------------------------------------------------------------------------
// Kernel 4: fused gate-mix + 1x1 conv (128x128) + bias + x*attn + residual.
// out = x * (0.5 + 0.5*(sum_c (wh*h + wv*v)[c] * fw[o][c] + fb[o]))
// Block 256 threads, tile = 128 pixels x 128 outs. Grid 2048.
// Dynamic smem: wT[128][129] + attn[128][128] = 132096 B.
// Inner product uses Blackwell packed fma.rn.f32x2 (2 pixels per FMA).
// ---------------------------------------------------------------------------
__global__ __launch_bounds__(256) void fuse_kernel(
    const float* __restrict__ x,
    const float* __restrict__ fw,
    const float* __restrict__ fb,
    float* __restrict__ out)
{
    extern __shared__ float smem[];
    float* wTs = smem;                 // [c][o], pitch 129 (conflict-free)
    float* as  = smem + 128 * 129;     // attn [c][128 pixels]

    const int t  = threadIdx.x;
    const int b  = blockIdx.x >> 9;
    const int p0 = (blockIdx.x & 511) << 7;

    const float wh = g_gate[b * 2 + 0];
    const float wv = g_gate[b * 2 + 1];

    // stage fuse_w transposed
    for (int i = t; i < 16384; i += 256) {
        int o = i >> 7, cc = i & 127;
        wTs[cc * 129 + o] = fw[i];
    }
    // stage attn tile = wh*h + wv*v
    const int base_b = b * Cc * PLANE + p0;
    for (int i = t; i < 4096; i += 256) {
        int c  = i >> 5;
        int pp = (i & 31) << 2;
        int idx = base_b + c * PLANE + pp;
        float4 hh = *(const float4*)(g_h + idx);
        float4 vv = *(const float4*)(g_v + idx);
        float4 a;
        a.x = wh * hh.x + wv * vv.x;
        a.y = wh * hh.y + wv * vv.y;
        a.z = wh * hh.z + wv * vv.z;
        a.w = wh * hh.w + wv * vv.w;
        *(float4*)(as + c * 128 + pp) = a;
    }
    __syncthreads();

    const int tx = t & 15;   // pixel-pair group
    const int ty = t >> 4;   // output-channel group

    unsigned long long acc[8][4];
#pragma unroll
    for (int j = 0; j < 8; j++)
#pragma unroll
        for (int q = 0; q < 4; q++) acc[j][q] = 0ull;

#pragma unroll 8
    for (int c = 0; c < 128; c++) {
        const unsigned long long* ar = (const unsigned long long*)(as + c * 128);
        unsigned long long a0 = ar[tx];
        unsigned long long a1 = ar[tx + 16];
        unsigned long long a2 = ar[tx + 32];
        unsigned long long a3 = ar[tx + 48];
        const float* wr = wTs + c * 129 + ty;
#pragma unroll
        for (int j = 0; j < 8; j++) {
            float w = wr[j * 16];
            unsigned long long wp;
            asm("mov.b64 %0, {%1, %1};" : "=l"(wp) : "f"(w));
            asm("fma.rn.f32x2 %0, %1, %2, %0;" : "+l"(acc[j][0]) : "l"(a0), "l"(wp));
            asm("fma.rn.f32x2 %0, %1, %2, %0;" : "+l"(acc[j][1]) : "l"(a1), "l"(wp));
            asm("fma.rn.f32x2 %0, %1, %2, %0;" : "+l"(acc[j][2]) : "l"(a2), "l"(wp));
            asm("fma.rn.f32x2 %0, %1, %2, %0;" : "+l"(acc[j][3]) : "l"(a3), "l"(wp));
        }
    }

    // epilogue: out = x * (0.5 + 0.5*(acc + fb))
#pragma unroll
    for (int j = 0; j < 8; j++) {
        const int o = ty + 16 * j;
        const float fbv = fb[o];
        const int rowbase = b * Cc * PLANE + o * PLANE + p0;
#pragma unroll
        for (int q = 0; q < 4; q++) {
            float s0, s1;
            asm("mov.b64 {%0, %1}, %2;" : "=f"(s0), "=f"(s1) : "l"(acc[j][q]));
            const int pix = 2 * (tx + 16 * q);
            const float2 xv = *(const float2*)(x + rowbase + pix);
            float2 r;
            r.x = xv.x * (0.5f + 0.5f * (s0 + fbv));
            r.y = xv.y * (0.5f + 0.5f * (s1 + fbv));
            *(float2*)(out + rowbase + pix) = r;
        }
    }
}

// ---------------------------------------------------------------------------
extern "C" void kernel_launch(void* const* d_in, const int* in_sizes, int n_in,
                              void* d_out, int out_size)
{
    const float* x   = (const float*)d_in[0];
    const float* h1w = (const float*)d_in[1];
    const float* h2w = (const float*)d_in[2];
    const float* v1w = (const float*)d_in[3];
    const float* v2w = (const float*)d_in[4];
    const float* g1w = (const float*)d_in[5];
    const float* g2w = (const float*)d_in[6];
    const float* g2b = (const float*)d_in[7];
    const float* fw  = (const float*)d_in[8];
    const float* fb  = (const float*)d_in[9];
    float* out = (float*)d_out;

    cudaFuncSetAttribute(vconv_kernel, cudaFuncAttributeMaxDynamicSharedMemorySize, 65536);
    cudaFuncSetAttribute(fuse_kernel,  cudaFuncAttributeMaxDynamicSharedMemorySize, 132096);

    hconv_kernel<<<dim3(64, 512), dim3(256, 4)>>>(x, h1w, h2w);
    vconv_kernel<<<dim3(8, 512), 256, 65536>>>(x, v1w, v2w);
    gate_kernel<<<1, 256>>>(g1w, g2w, g2b);
    fuse_kernel<<<2048, 256, 132096>>>(x, fw, fb, out);
}

// round 7
// speedup vs baseline: 1.4288x; 1.4288x over previous
#include <cuda_runtime.h>
#include <cuda_fp16.h>
#include <cstdint>

// Problem constants
#define Cc      128
#define Hh      256
#define Ww      256
#define Bb      4
#define PLANE   65536          // Hh*Ww
#define NPLANES 512            // Bb*Cc
#define TOTAL   33554432       // Bb*Cc*PLANE

// Scratch (allocation-free rule: __device__ globals)
__device__ __half g_h[TOTAL];
__device__ __half g_v[TOTAL];
__device__ float  g_hpart[NPLANES * 32];
__device__ float  g_vpart[NPLANES * 8];
__device__ float  g_gate[Bb * 2];

typedef unsigned long long u64;

// ---------------------------------------------------------------------------
// Kernel 1: horizontal chain  h = dw1x5(x) then dw1x7 dil3.
// Zero-padded smem, and ys pad region EXPLICITLY ZERO (reference zero-pads the
// intermediate between the two convs). Block (64,8)=512 thr. Grid (32,512).
// ---------------------------------------------------------------------------
__global__ __launch_bounds__(512) void hconv_kernel(
    const float* __restrict__ x,
    const float* __restrict__ h1w,
    const float* __restrict__ h2w)
{
    // xs: [0..11]=0, [12..267]=x[0..255], [268..279]=0.
    // ys index i ~ y col (i-9); valid y cols [0,256) -> i in [9,265);
    // i in [0,9) and [265,276) are ZERO (reference inter-stage zero padding).
    __shared__ float xs[8][280];
    __shared__ float ys[8][276];
    __shared__ float red[16];

    const int plane = blockIdx.y;
    const int rb    = blockIdx.x;          // 0..31, 8 rows each
    const int c     = plane & (Cc - 1);
    const int tx    = threadIdx.x;         // 0..63
    const int ty    = threadIdx.y;         // 0..7
    const int row   = rb * 8 + ty;

    float w1[5], w2[7];
#pragma unroll
    for (int j = 0; j < 5; j++) w1[j] = h1w[c * 5 + j];
#pragma unroll
    for (int k = 0; k < 7; k++) w2[k] = h2w[c * 7 + k];

    const int base = plane * PLANE + row * Ww;

    *(float4*)&xs[ty][12 + 4 * tx] = *(const float4*)(x + base + 4 * tx);
    if (tx < 3)       *(float4*)&xs[ty][4 * tx] = make_float4(0.f, 0.f, 0.f, 0.f);
    else if (tx < 6)  *(float4*)&xs[ty][268 + 4 * (tx - 3)] = make_float4(0.f, 0.f, 0.f, 0.f);
    // zero ys pads
    if (tx < 9)  ys[ty][tx] = 0.f;
    if (tx < 11) ys[ty][265 + tx] = 0.f;
    __syncthreads();

    // stage 1: valid region only, i in [9,265)  (4 iters exactly)
#pragma unroll
    for (int q = 0; q < 4; q++) {
        const int i = 9 + tx + 64 * q;
        float y = 0.f;
#pragma unroll
        for (int j = 0; j < 5; j++) y += xs[ty][i + 1 + j] * w1[j];
        ys[ty][i] = y;
    }
    __syncthreads();

    // stage 2: h[px] = sum_k ys[px+3k]*w2[k]
    float acc = 0.f;
#pragma unroll
    for (int q = 0; q < 4; q++) {
        const int px = tx + 64 * q;
        float v = 0.f;
#pragma unroll
        for (int k = 0; k < 7; k++) v += ys[ty][px + 3 * k] * w2[k];
        g_h[base + px] = __float2half(v);
        acc += v;
    }

    // block reduction (512 threads)
#pragma unroll
    for (int o = 16; o > 0; o >>= 1) acc += __shfl_down_sync(0xffffffffu, acc, o);
    const int t    = ty * 64 + tx;
    const int wid  = t >> 5;
    const int lane = t & 31;
    if (lane == 0) red[wid] = acc;
    __syncthreads();
    if (wid == 0) {
        float v = (lane < 16) ? red[lane] : 0.f;
#pragma unroll
        for (int o = 8; o > 0; o >>= 1) v += __shfl_down_sync(0xffffffffu, v, o);
        if (lane == 0) g_hpart[plane * 32 + rb] = v;
    }
}

// ---------------------------------------------------------------------------
// Kernel 2: vertical chain, same zero-pad semantics for ys rows.
// Block 256, tile 32 cols x 256 rows. Grid (8,512). Smem 70656 B.
// ---------------------------------------------------------------------------
__global__ __launch_bounds__(256) void vconv_kernel(
    const float* __restrict__ x,
    const float* __restrict__ v1w,
    const float* __restrict__ v2w)
{
    extern __shared__ float vsm[];
    float* xs = vsm;            // [278][32], row rx ~ x row rx-11 (0 outside)
    float* ys = vsm + 278 * 32; // [274][32], row i ~ y row i-9; pads ZERO

    const int plane = blockIdx.y;
    const int tile  = blockIdx.x;
    const int c     = plane & (Cc - 1);
    const int c0    = tile * 32;
    const int t     = threadIdx.x;

    float w1[5], w2[7];
#pragma unroll
    for (int j = 0; j < 5; j++) w1[j] = v1w[c * 5 + j];
#pragma unroll
    for (int k = 0; k < 7; k++) w2[k] = v2w[c * 7 + k];

    const int pbase = plane * PLANE + c0;
    for (int i = t; i < 278 * 32; i += 256) {
        int rx = i >> 5, cl = i & 31;
        int r  = rx - 11;
        xs[i] = (r >= 0 && r < Hh) ? x[pbase + r * Ww + cl] : 0.f;
    }
    // zero ys pad rows: i in [0,9) and [265,274)  (9*32=288 elems each)
    for (int i = t; i < 288; i += 256) {
        ys[i] = 0.f;
        ys[265 * 32 + i] = 0.f;
    }
    __syncthreads();

    const int rr = t >> 5;
    const int cl = t & 31;

    // stage 1: valid y rows only: i in [9,265)
    for (int rp = 9 + rr; rp < 265; rp += 8) {
        float s = 0.f;
#pragma unroll
        for (int j = 0; j < 5; j++) s += xs[(rp + j) * 32 + cl] * w1[j];
        ys[rp * 32 + cl] = s;
    }
    __syncthreads();

    // stage 2: v[r] = sum_k ys[r+3k]*w2[k]
    float acc = 0.f;
    for (int r = rr; r < Hh; r += 8) {
        float s = 0.f;
#pragma unroll
        for (int k = 0; k < 7; k++) s += ys[(r + 3 * k) * 32 + cl] * w2[k];
        g_v[pbase + r * Ww + cl] = __float2half(s);
        acc += s;
    }

    __shared__ float red[8];
#pragma unroll
    for (int o = 16; o > 0; o >>= 1) acc += __shfl_down_sync(0xffffffffu, acc, o);
    const int wid = t >> 5, lane = t & 31;
    if (lane == 0) red[wid] = acc;
    __syncthreads();
    if (wid == 0) {
        float v = (lane < 8) ? red[lane] : 0.f;
#pragma unroll
        for (int o = 4; o > 0; o >>= 1) v += __shfl_down_sync(0xffffffffu, v, o);
        if (lane == 0) g_vpart[plane * 8 + tile] = v;
    }
}

// ---------------------------------------------------------------------------
// Kernel 3: gate. One block, 256 threads.
// ---------------------------------------------------------------------------
__global__ __launch_bounds__(256) void gate_kernel(
    const float* __restrict__ g1w,
    const float* __restrict__ g2w,
    const float* __restrict__ g2b)
{
    __shared__ float pooled[Bb][2 * Cc];
    __shared__ float gs[Bb][32];
    const int t = threadIdx.x;
    const float inv = 1.0f / 65536.0f;

    for (int p = t; p < NPLANES; p += 256) {
        int b = p >> 7, c = p & 127;
        float hs = 0.f;
#pragma unroll
        for (int i = 0; i < 32; i++) hs += g_hpart[p * 32 + i];
        float vs = 0.f;
#pragma unroll
        for (int i = 0; i < 8; i++) vs += g_vpart[p * 8 + i];
        pooled[b][c]      = hs * inv;
        pooled[b][Cc + c] = vs * inv;
    }
    __syncthreads();

    if (t < 128) {
        int b = t >> 5, j = t & 31;
        float s = 0.f;
        for (int i = 0; i < 2 * Cc; i++) s += pooled[b][i] * g1w[j * 256 + i];
        gs[b][j] = s / (1.0f + expf(-s));   // SiLU
    }
    __syncthreads();

    if (t < Bb) {
        int b = t;
        float l0 = g2b[0], l1 = g2b[1];
        for (int j = 0; j < 32; j++) {
            l0 += gs[b][j] * g2w[j];
            l1 += gs[b][j] * g2w[32 + j];
        }
        float m = fmaxf(l0, l1);
        float e0 = expf(l0 - m), e1 = expf(l1 - m);
        float d = e0 + e1;
        g_gate[b * 2 + 0] = e0 / d;
        g_gate[b * 2 + 1] = e1 / d;
    }
}

// ---------------------------------------------------------------------------
// Kernel 4: gate-mix + 1x1 conv + bias + x*attn + residual.
// Tile 256 pixels x 128 outs, 512 threads, per thread 8px x 8o.
// Dynamic smem: wTs[128][129] + as[128][256] = 197120 B.
// fp32x2 packed FMA mainloop.
// ---------------------------------------------------------------------------
__global__ __launch_bounds__(512) void fuse_kernel(
    const float* __restrict__ x,
    const float* __restrict__ fw,
    const float* __restrict__ fb,
    float* __restrict__ out)
{
    extern __shared__ float smem[];
    float* wTs = smem;                 // [c][o], pitch 129 (conflict-free)
    float* as  = smem + 128 * 129;     // attn [c][256 px]

    const int t  = threadIdx.x;
    const int b  = blockIdx.x >> 8;
    const int p0 = (blockIdx.x & 255) << 8;

    const float wh = g_gate[b * 2 + 0];
    const float wv = g_gate[b * 2 + 1];

    // stage fuse_w transposed
    for (int i = t; i < 16384; i += 512) {
        int o = i >> 7, cc = i & 127;
        wTs[cc * 129 + o] = fw[i];
    }
    // stage attn tile = wh*h + wv*v (fp16 -> fp32)
    const int base_b = b * (Cc * PLANE) + p0;
    for (int i = t; i < 4096; i += 512) {
        int c  = i >> 5;
        int pp = (i & 31) << 3;                  // 8 px chunk
        const __half2* hp = (const __half2*)(g_h + base_b + c * PLANE + pp);
        const __half2* vp = (const __half2*)(g_v + base_b + c * PLANE + pp);
        float* dst = as + c * 256 + pp;
#pragma unroll
        for (int u = 0; u < 4; u++) {
            float2 hf = __half22float2(hp[u]);
            float2 vf = __half22float2(vp[u]);
            dst[2 * u + 0] = wh * hf.x + wv * vf.x;
            dst[2 * u + 1] = wh * hf.y + wv * vf.y;
        }
    }
    __syncthreads();

    const int tx = t & 31;   // pixel-pair slot (pairs tx, tx+32, tx+64, tx+96)
    const int ty = t >> 5;   // out-group (outs ty + 16j)

    u64 acc[8][4];
#pragma unroll
    for (int j = 0; j < 8; j++)
#pragma unroll
        for (int q = 0; q < 4; q++) acc[j][q] = 0ull;

#pragma unroll 4
    for (int c = 0; c < 128; c++) {
        const u64* ar = (const u64*)as + c * 128;
        u64 a0 = ar[tx];
        u64 a1 = ar[tx + 32];
        u64 a2 = ar[tx + 64];
        u64 a3 = ar[tx + 96];
        const float* wr = wTs + c * 129 + ty;
#pragma unroll
        for (int j = 0; j < 8; j++) {
            float w = wr[j * 16];
            u64 wp;
            asm("mov.b64 %0, {%1, %1};" : "=l"(wp) : "f"(w));
            asm("fma.rn.f32x2 %0, %1, %2, %0;" : "+l"(acc[j][0]) : "l"(a0), "l"(wp));
            asm("fma.rn.f32x2 %0, %1, %2, %0;" : "+l"(acc[j][1]) : "l"(a1), "l"(wp));
            asm("fma.rn.f32x2 %0, %1, %2, %0;" : "+l"(acc[j][2]) : "l"(a2), "l"(wp));
            asm("fma.rn.f32x2 %0, %1, %2, %0;" : "+l"(acc[j][3]) : "l"(a3), "l"(wp));
        }
    }

    // epilogue: out = x * (0.5 + 0.5*(acc + fb))
#pragma unroll
    for (int j = 0; j < 8; j++) {
        const int o = ty + 16 * j;
        const float fbv = fb[o];
        const int rowbase = b * (Cc * PLANE) + o * PLANE + p0;
#pragma unroll
        for (int q = 0; q < 4; q++) {
            float s0, s1;
            asm("mov.b64 {%0, %1}, %2;" : "=f"(s0), "=f"(s1) : "l"(acc[j][q]));
            const int pix = 2 * (tx + 32 * q);
            const float2 xv = *(const float2*)(x + rowbase + pix);
            float2 r;
            r.x = xv.x * (0.5f + 0.5f * (s0 + fbv));
            r.y = xv.y * (0.5f + 0.5f * (s1 + fbv));
            *(float2*)(out + rowbase + pix) = r;
        }
    }
}

// ---------------------------------------------------------------------------
extern "C" void kernel_launch(void* const* d_in, const int* in_sizes, int n_in,
                              void* d_out, int out_size)
{
    const float* x   = (const float*)d_in[0];
    const float* h1w = (const float*)d_in[1];
    const float* h2w = (const float*)d_in[2];
    const float* v1w = (const float*)d_in[3];
    const float* v2w = (const float*)d_in[4];
    const float* g1w = (const float*)d_in[5];
    const float* g2w = (const float*)d_in[6];
    const float* g2b = (const float*)d_in[7];
    const float* fw  = (const float*)d_in[8];
    const float* fb  = (const float*)d_in[9];
    float* out = (float*)d_out;

    cudaFuncSetAttribute(vconv_kernel, cudaFuncAttributeMaxDynamicSharedMemorySize, 70656);
    cudaFuncSetAttribute(fuse_kernel,  cudaFuncAttributeMaxDynamicSharedMemorySize, 197120);

    hconv_kernel<<<dim3(32, 512), dim3(64, 8)>>>(x, h1w, h2w);
    vconv_kernel<<<dim3(8, 512), 256, 70656>>>(x, v1w, v2w);
    gate_kernel<<<1, 256>>>(g1w, g2w, g2b);
    fuse_kernel<<<1024, 512, 197120>>>(x, fw, fb, out);
}

// round 9
// speedup vs baseline: 1.6514x; 1.1558x over previous
#include <cuda_runtime.h>
#include <cuda_fp16.h>
#include <cstdint>

// Problem constants
#define Cc      128
#define Hh      256
#define Ww      256
#define Bb      4
#define PLANE   65536          // Hh*Ww
#define NPLANES 512            // Bb*Cc
#define TOTAL   33554432       // Bb*Cc*PLANE

// Scratch (allocation-free rule: __device__ globals)
__device__ __half g_h[TOTAL];
__device__ __half g_v[TOTAL];
__device__ float  g_hpart[NPLANES * 32];
__device__ float  g_vpart[NPLANES * 8];
__device__ float  g_gate[Bb * 2];

typedef unsigned long long u64;

// ---------------------------------------------------------------------------
// Kernel 1: horizontal chain  h = dw1x5(x) then dw1x7 dil3.
// One WARP per image row; per-warp smem slices; __syncwarp only.
// Block (32,8) = 256 thr = 8 rows. Grid (32, 512).
// ys zero-padded to match reference inter-stage zero padding exactly.
// ---------------------------------------------------------------------------
__global__ __launch_bounds__(256) void hconv_kernel(
    const float* __restrict__ x,
    const float* __restrict__ h1w,
    const float* __restrict__ h2w)
{
    // xs: [0..11]=0, [12..267]=x[0..255], [268..279]=0.
    // ys index i ~ y col (i-9); valid cols -> i in [9,265); pads ZERO.
    __shared__ float xs[8][280];
    __shared__ float ys[8][280];
    __shared__ float red[8];

    const int plane = blockIdx.y;
    const int rb    = blockIdx.x;          // 0..31, 8 rows each
    const int c     = plane & (Cc - 1);
    const int l     = threadIdx.x;         // lane 0..31
    const int wrp   = threadIdx.y;         // warp 0..7 (its own row)
    const int row   = rb * 8 + wrp;

    float w1[5], w2[7];
#pragma unroll
    for (int j = 0; j < 5; j++) w1[j] = h1w[c * 5 + j];
#pragma unroll
    for (int k = 0; k < 7; k++) w2[k] = h2w[c * 7 + k];

    const int base = plane * PLANE + row * Ww;

    // load row (2 x LDG.128 per lane), pads
    *(float4*)&xs[wrp][12 + 4 * l]  = *(const float4*)(x + base + 4 * l);
    *(float4*)&xs[wrp][140 + 4 * l] = *(const float4*)(x + base + 128 + 4 * l);
    if (l < 3) {
        *(float4*)&xs[wrp][4 * l]       = make_float4(0.f, 0.f, 0.f, 0.f);
        *(float4*)&xs[wrp][268 + 4 * l] = make_float4(0.f, 0.f, 0.f, 0.f);
    }
    if (l < 9)  ys[wrp][l] = 0.f;
    if (l < 11) ys[wrp][265 + l] = 0.f;
    __syncwarp();

    // stage 1: valid region i in [9,265), 8 px per thread
#pragma unroll
    for (int q = 0; q < 8; q++) {
        const int i = 9 + l + 32 * q;
        float y = 0.f;
#pragma unroll
        for (int j = 0; j < 5; j++) y += xs[wrp][i + 1 + j] * w1[j];
        ys[wrp][i] = y;
    }
    __syncwarp();

    // stage 2
    float acc = 0.f;
#pragma unroll
    for (int q = 0; q < 8; q++) {
        const int px = l + 32 * q;
        float v = 0.f;
#pragma unroll
        for (int k = 0; k < 7; k++) v += ys[wrp][px + 3 * k] * w2[k];
        g_h[base + px] = __float2half(v);
        acc += v;
    }

    // warp reduce, then tiny cross-warp combine
#pragma unroll
    for (int o = 16; o > 0; o >>= 1) acc += __shfl_down_sync(0xffffffffu, acc, o);
    if (l == 0) red[wrp] = acc;
    __syncthreads();
    if (wrp == 0 && l == 0) {
        float s = 0.f;
#pragma unroll
        for (int i = 0; i < 8; i++) s += red[i];
        g_hpart[plane * 32 + rb] = s;
    }
}

// ---------------------------------------------------------------------------
// Kernel 2: vertical chain, PURE-REGISTER sliding windows (no smem, no sync).
// Each warp owns a 32-col x 256-row strip; lane = column. x-ring 7, y-ring 21;
// row loop unrolled by 21 -> all ring indices compile-time constants.
// y rows outside [0,256) are forced to ZERO (reference inter-stage padding).
// Grid 512 blocks x 256 thr (8 warps each); warp -> (plane, 32-col tile).
// ---------------------------------------------------------------------------
__global__ __launch_bounds__(256) void vconv_kernel(
    const float* __restrict__ x,
    const float* __restrict__ v1w,
    const float* __restrict__ v2w)
{
    const int t   = threadIdx.x;
    const int l   = t & 31;
    const int w   = t >> 5;
    const int idx = blockIdx.x * 8 + w;    // 0..4095
    const int plane = idx >> 3;
    const int tile  = idx & 7;
    const int c     = plane & (Cc - 1);

    float w1[5], w2[7];
#pragma unroll
    for (int j = 0; j < 5; j++) w1[j] = v1w[c * 5 + j];
#pragma unroll
    for (int k = 0; k < 7; k++) w2[k] = v2w[c * 7 + k];

    const float* xp  = x + plane * PLANE + tile * 32 + l;
    __half* vout = g_v + plane * PLANE + tile * 32 + l;

    float Y[21];
    float X[7];
#pragma unroll
    for (int i = 0; i < 21; i++) Y[i] = 0.f;

    // prologue: x rows 0..10; y rows 0..8 (slot = row % 21)
    float xv[11];
#pragma unroll
    for (int r = 0; r < 11; r++) xv[r] = xp[r * Ww];
#pragma unroll
    for (int ry = 0; ry < 9; ry++) {
        float s = 0.f;
#pragma unroll
        for (int j = 0; j < 5; j++) {
            int q = ry + j - 2;
            if (q >= 0) s += xv[q] * w1[j];
        }
        Y[ry] = s;
    }
    // x ring holds rows 7..10 at slots (row % 7)
#pragma unroll
    for (int r = 7; r < 11; r++) X[r % 7] = xv[r];

    float accg = 0.f;

    // main: 13 blocks x 21 = 273 steps (emits s = 0..255, rest predicated off)
#pragma unroll 1
    for (int sb = 0; sb < 273; sb += 21) {
#pragma unroll
        for (int u = 0; u < 21; u++) {
            const int s = sb + u;
            // load x row s+11 (slot (s+11)%7 = (u+4)%7), zero past bottom
            const int xrow = s + 11;
            float xn = xp[(xrow < 256 ? xrow : 255) * Ww];
            if (xrow > 255) xn = 0.f;
            X[(u + 4) % 7] = xn;
            // y row s+9 from x rows s+7..s+11
            float yv = X[(u + 0) % 7] * w1[0] + X[(u + 1) % 7] * w1[1]
                     + X[(u + 2) % 7] * w1[2] + X[(u + 3) % 7] * w1[3]
                     + X[(u + 4) % 7] * w1[4];
            if (s + 9 > 255) yv = 0.f;
            Y[(u + 9) % 21] = yv;
            // v[s] = sum_k y[s-9+3k] * w2[k]   (slot (s+12+3k)%21)
            float v = Y[(u + 12) % 21] * w2[0] + Y[(u + 15) % 21] * w2[1]
                    + Y[(u + 18) % 21] * w2[2] + Y[(u + 0)  % 21] * w2[3]
                    + Y[(u + 3)  % 21] * w2[4] + Y[(u + 6)  % 21] * w2[5]
                    + Y[(u + 9)  % 21] * w2[6];
            if (s < 256) {
                vout[s * Ww] = __float2half(v);
                accg += v;
            }
        }
    }

    // warp reduce -> per (plane,tile) partial
#pragma unroll
    for (int o = 16; o > 0; o >>= 1) accg += __shfl_down_sync(0xffffffffu, accg, o);
    if (l == 0) g_vpart[idx] = accg;
}

// ---------------------------------------------------------------------------
// Kernel 3: gate. One block, 256 threads.
// ---------------------------------------------------------------------------
__global__ __launch_bounds__(256) void gate_kernel(
    const float* __restrict__ g1w,
    const float* __restrict__ g2w,
    const float* __restrict__ g2b)
{
    __shared__ float pooled[Bb][2 * Cc];
    __shared__ float gs[Bb][32];
    const int t = threadIdx.x;
    const float inv = 1.0f / 65536.0f;

    for (int p = t; p < NPLANES; p += 256) {
        int b = p >> 7, c = p & 127;
        float hs = 0.f;
#pragma unroll
        for (int i = 0; i < 32; i++) hs += g_hpart[p * 32 + i];
        float vs = 0.f;
#pragma unroll
        for (int i = 0; i < 8; i++) vs += g_vpart[p * 8 + i];
        pooled[b][c]      = hs * inv;
        pooled[b][Cc + c] = vs * inv;
    }
    __syncthreads();

    if (t < 128) {
        int b = t >> 5, j = t & 31;
        float s = 0.f;
        for (int i = 0; i < 2 * Cc; i++) s += pooled[b][i] * g1w[j * 256 + i];
        gs[b][j] = s / (1.0f + expf(-s));   // SiLU
    }
    __syncthreads();

    if (t < Bb) {
        int b = t;
        float l0 = g2b[0], l1 = g2b[1];
        for (int j = 0; j < 32; j++) {
            l0 += gs[b][j] * g2w[j];
            l1 += gs[b][j] * g2w[32 + j];
        }
        float m = fmaxf(l0, l1);
        float e0 = expf(l0 - m), e1 = expf(l1 - m);
        float d = e0 + e1;
        g_gate[b * 2 + 0] = e0 / d;
        g_gate[b * 2 + 1] = e1 / d;
    }
}

// ---------------------------------------------------------------------------
// Kernel 4: gate-mix + 1x1 conv + bias + x*attn + residual.
// Tile 256 px x 128 outs, 512 threads, per thread 8 px x 8 CONTIGUOUS outs.
// All mainloop smem via LDS.128: per warp per c = 8 wf (a) + 2 wf (w bcast)
// vs 16 fma-cyc -> fma-pipe-bound. Smem: wTs[128][132] + as[128][256].
// ---------------------------------------------------------------------------
__global__ __launch_bounds__(512) void fuse_kernel(
    const float* __restrict__ x,
    const float* __restrict__ fw,
    const float* __restrict__ fb,
    float* __restrict__ out)
{
    extern __shared__ float smem[];
    float* wTs = smem;                 // [c][o], pitch 132 (16B-aligned rows)
    float* as  = smem + 128 * 132;     // attn [c][256 px]

    const int t  = threadIdx.x;
    const int b  = blockIdx.x >> 8;
    const int p0 = (blockIdx.x & 255) << 8;

    const float wh = g_gate[b * 2 + 0];
    const float wv = g_gate[b * 2 + 1];

    // stage fuse_w transposed: wTs[c][o] = fw[o][c]
    for (int i = t; i < 16384; i += 512) {
        int o = i >> 7, cc = i & 127;
        wTs[cc * 132 + o] = fw[i];
    }
    // stage attn tile = wh*h + wv*v (fp16 -> fp32), vectorized 8-px chunks
    const int base_b = b * (Cc * PLANE) + p0;
    for (int i = t; i < 4096; i += 512) {
        int cc = i >> 5;
        int pp = (i & 31) << 3;                  // 8 px chunk
        uint4 H = *(const uint4*)(g_h + base_b + cc * PLANE + pp);
        uint4 V = *(const uint4*)(g_v + base_b + cc * PLANE + pp);
        float* dst = as + cc * 256 + pp;
        float4 r0, r1;
        {
            float2 hf, vf;
            hf = __half22float2(*(__half2*)&H.x); vf = __half22float2(*(__half2*)&V.x);
            r0.x = wh * hf.x + wv * vf.x; r0.y = wh * hf.y + wv * vf.y;
            hf = __half22float2(*(__half2*)&H.y); vf = __half22float2(*(__half2*)&V.y);
            r0.z = wh * hf.x + wv * vf.x; r0.w = wh * hf.y + wv * vf.y;
            hf = __half22float2(*(__half2*)&H.z); vf = __half22float2(*(__half2*)&V.z);
            r1.x = wh * hf.x + wv * vf.x; r1.y = wh * hf.y + wv * vf.y;
            hf = __half22float2(*(__half2*)&H.w); vf = __half22float2(*(__half2*)&V.w);
            r1.z = wh * hf.x + wv * vf.x; r1.w = wh * hf.y + wv * vf.y;
        }
        *(float4*)(dst)     = r0;
        *(float4*)(dst + 4) = r1;
    }
    __syncthreads();

    const int tx = t & 31;   // px group: 4tx..4tx+3 and 4tx+128..131
    const int ty = t >> 5;   // outs 8*ty .. 8*ty+7

    u64 acc[8][4];
#pragma unroll
    for (int j = 0; j < 8; j++)
#pragma unroll
        for (int q = 0; q < 4; q++) acc[j][q] = 0ull;

#pragma unroll 2
    for (int c = 0; c < 128; c++) {
        const float* arow = as + c * 256;
        ulonglong2 A0 = *(const ulonglong2*)(arow + 4 * tx);        // px 4tx..+3
        ulonglong2 A1 = *(const ulonglong2*)(arow + 4 * tx + 128);  // px +128
        const float* wrow = wTs + c * 132 + 8 * ty;
        float4 w03 = *(const float4*)(wrow);        // broadcast LDS.128
        float4 w47 = *(const float4*)(wrow + 4);    // broadcast LDS.128
        float wj[8] = {w03.x, w03.y, w03.z, w03.w, w47.x, w47.y, w47.z, w47.w};
#pragma unroll
        for (int j = 0; j < 8; j++) {
            u64 wp;
            asm("mov.b64 %0, {%1, %1};" : "=l"(wp) : "f"(wj[j]));
            asm("fma.rn.f32x2 %0, %1, %2, %0;" : "+l"(acc[j][0]) : "l"(A0.x), "l"(wp));
            asm("fma.rn.f32x2 %0, %1, %2, %0;" : "+l"(acc[j][1]) : "l"(A0.y), "l"(wp));
            asm("fma.rn.f32x2 %0, %1, %2, %0;" : "+l"(acc[j][2]) : "l"(A1.x), "l"(wp));
            asm("fma.rn.f32x2 %0, %1, %2, %0;" : "+l"(acc[j][3]) : "l"(A1.y), "l"(wp));
        }
    }

    // epilogue: out = x * (0.5 + 0.5*(acc + fb)), float4 I/O
#pragma unroll
    for (int j = 0; j < 8; j++) {
        const int o = 8 * ty + j;
        const float fbv = fb[o];
        const int rowbase = b * (Cc * PLANE) + o * PLANE + p0;
#pragma unroll
        for (int g = 0; g < 2; g++) {
            float s0, s1, s2, s3;
            asm("mov.b64 {%0, %1}, %2;" : "=f"(s0), "=f"(s1) : "l"(acc[j][2 * g + 0]));
            asm("mov.b64 {%0, %1}, %2;" : "=f"(s2), "=f"(s3) : "l"(acc[j][2 * g + 1]));
            const int pix = 4 * tx + 128 * g;
            const float4 xv = *(const float4*)(x + rowbase + pix);
            float4 r;
            r.x = xv.x * (0.5f + 0.5f * (s0 + fbv));
            r.y = xv.y * (0.5f + 0.5f * (s1 + fbv));
            r.z = xv.z * (0.5f + 0.5f * (s2 + fbv));
            r.w = xv.w * (0.5f + 0.5f * (s3 + fbv));
            *(float4*)(out + rowbase + pix) = r;
        }
    }
}

// ---------------------------------------------------------------------------
extern "C" void kernel_launch(void* const* d_in, const int* in_sizes, int n_in,
                              void* d_out, int out_size)
{
    const float* x   = (const float*)d_in[0];
    const float* h1w = (const float*)d_in[1];
    const float* h2w = (const float*)d_in[2];
    const float* v1w = (const float*)d_in[3];
    const float* v2w = (const float*)d_in[4];
    const float* g1w = (const float*)d_in[5];
    const float* g2w = (const float*)d_in[6];
    const float* g2b = (const float*)d_in[7];
    const float* fw  = (const float*)d_in[8];
    const float* fb  = (const float*)d_in[9];
    float* out = (float*)d_out;

    cudaFuncSetAttribute(fuse_kernel, cudaFuncAttributeMaxDynamicSharedMemorySize, 198656);

    hconv_kernel<<<dim3(32, 512), dim3(32, 8)>>>(x, h1w, h2w);
    vconv_kernel<<<512, 256>>>(x, v1w, v2w);
    gate_kernel<<<1, 256>>>(g1w, g2w, g2b);
    fuse_kernel<<<1024, 512, 198656>>>(x, fw, fb, out);
}